// round 7
// baseline (speedup 1.0000x reference)
#include <cuda_runtime.h>
#include <cstdint>

// ---------------------------------------------------------------------------
// Swin WindowAttention, fused per-window TF32 mma.sync kernel, round 7.
// Crossbar-byte-optimized: GEMM1/GEMM4 use 8 warps with 32x32 warp tiles
// (256 B smem traffic per mma), remaining warps prefetch weights to regs.
// Attention phase (register softmax, per-warp P scratch) as in round 6.
// ---------------------------------------------------------------------------

namespace {
constexpr int NTOK  = 49;
constexpr int CDIM  = 128;
constexpr int NHEAD = 4;
constexpr int TC3   = 384;
constexpr int MAXW  = 64;
constexpr int S136  = 136;   // operand stride (%32==8)
constexpr int SVT   = 72;    // V-transposed stride
constexpr int SP    = 72;    // per-warp P scratch stride

constexpr int OFF_Q  = 0;                    // [64][136]
constexpr int OFF_K  = OFF_Q  + 64 * S136;   // [64][136]
constexpr int OFF_VT = OFF_K  + 64 * S136;   // [128][72]
constexpr int OFF_XS = OFF_VT + 128 * SVT;   // [64][136] x, then attn-out
constexpr int OFF_WB = OFF_XS + 64 * S136;   // W slice [128][136] / P scratch
constexpr int WBREG  = 16 * 16 * SP;         // 18432 >= 128*136=17408
constexpr int SMEMF  = OFF_WB + WBREG;       // 53760 floats = 215040 B
}

__device__ float g_wqkv_t[TC3 * CDIM];             // [n=384][pk(k=128)]
__device__ float g_wproj_t[CDIM * CDIM];           // [n=128][pk(k=128)]
__device__ float g_rm[MAXW * NHEAD * 64 * 64];     // rpb+mask, padded with -1e30

__device__ __host__ __forceinline__ int pk(int c) {
    return (c & ~7) | ((c & 3) << 1) | ((c >> 2) & 1);
}

__device__ __forceinline__ float tfs(float f) {
    unsigned r;
    asm("cvt.rna.tf32.f32 %0, %1;" : "=r"(r) : "f"(f));
    return __uint_as_float(r);
}

__device__ __forceinline__ void mma8(float* c, float a0, float a1, float a2, float a3,
                                     float b0, float b1) {
    asm volatile(
        "mma.sync.aligned.m16n8k8.row.col.f32.tf32.tf32.f32 "
        "{%0,%1,%2,%3}, {%4,%5,%6,%7}, {%8,%9}, {%0,%1,%2,%3};"
        : "+f"(c[0]), "+f"(c[1]), "+f"(c[2]), "+f"(c[3])
        : "r"(__float_as_uint(a0)), "r"(__float_as_uint(a1)),
          "r"(__float_as_uint(a2)), "r"(__float_as_uint(a3)),
          "r"(__float_as_uint(b0)), "r"(__float_as_uint(b1)));
}

// ---------------- prepack kernels ------------------------------------------
__global__ void prepack_w(const float* __restrict__ qkv_w,
                          const float* __restrict__ proj_w) {
    int t = blockIdx.x * blockDim.x + threadIdx.x;
    if (t < TC3 * CDIM) {
        int n = t % TC3, k = t / TC3;
        g_wqkv_t[n * CDIM + pk(k)] = tfs(qkv_w[k * TC3 + n]);
    } else {
        int t2 = t - TC3 * CDIM;
        if (t2 < CDIM * CDIM) {
            int n = t2 % CDIM, k = t2 / CDIM;
            g_wproj_t[n * CDIM + pk(k)] = tfs(proj_w[k * CDIM + n]);
        }
    }
}

__global__ void prepack_rm(const float* __restrict__ mask,
                           const float* __restrict__ bias_t, int nmask) {
    int t = blockIdx.x * blockDim.x + threadIdx.x;
    int total = nmask * NHEAD * 64 * 64;
    if (t >= total) return;
    int j = t & 63;
    int i = (t >> 6) & 63;
    int h = (t >> 12) & (NHEAD - 1);
    int v = t >> 14;
    float val = -1.0e30f;
    if (i < NTOK && j < NTOK) {
        int ri = i / 7, ci = i - ri * 7;
        int rj = j / 7, cj = j - rj * 7;
        int idx = (ri - rj + 6) * 13 + (ci - cj + 6);
        val = bias_t[idx * NHEAD + h] + mask[(size_t)v * NTOK * NTOK + i * NTOK + j];
    }
    g_rm[t] = val;
}

// ---------------- main kernel ---------------------------------------------
__global__ __launch_bounds__(1024, 1) void win_attn_kernel(
    const float* __restrict__ x,      const float* __restrict__ qkv_b,
    const float* __restrict__ proj_b, float* __restrict__ out, int nmask)
{
    extern __shared__ float sm[];
    float* Qb = sm + OFF_Q;
    float* Kb = sm + OFF_K;
    float* VT = sm + OFF_VT;
    float* XS = sm + OFF_XS;
    float* WB = sm + OFF_WB;

    const int w    = blockIdx.x;
    const int tid  = threadIdx.x;
    const int warp = tid >> 5;
    const int lane = tid & 31;
    const int g    = lane >> 2;
    const int tig  = lane & 3;
    const int tg2  = tig * 2;

    // ---------------- phase 0: stage x packed; zero pads --------------------
    {
        const float* xg = x + (size_t)w * NTOK * CDIM;
        if (tid < NTOK * 16) {
            int r = tid >> 4, gb = (tid & 15) * 8;
            float4 v0 = *(const float4*)(xg + r * CDIM + gb);
            float4 v1 = *(const float4*)(xg + r * CDIM + gb + 4);
            float* d = XS + r * S136 + gb;
            *(float4*)(d)     = make_float4(tfs(v0.x), tfs(v1.x), tfs(v0.y), tfs(v1.y));
            *(float4*)(d + 4) = make_float4(tfs(v0.z), tfs(v1.z), tfs(v0.w), tfs(v1.w));
        }
        for (int u = tid; u < 15 * S136; u += 1024)      // XS pad rows = 0
            XS[NTOK * S136 + u] = 0.0f;
        if (tid < CDIM * 8) {                            // VT pad tokens 48..55 = 0
            int ch = tid >> 3, t = 48 + (tid & 7);
            VT[ch * SVT + pk(t)] = 0.0f;                 // t=48 overwritten later
        }
    }

    const float4* wsrc = (const float4*)g_wqkv_t;
    float4 pfr[8];

    // stage W slice 0 (all threads: 4096 float4)
#pragma unroll
    for (int u = 0; u < 4; u++) pfr[u] = wsrc[u * 1024 + tid];
#pragma unroll
    for (int u = 0; u < 4; u++) {
        int idx = u * 1024 + tid;
        *(float4*)(WB + (idx >> 5) * S136 + (idx & 31) * 4) = pfr[u];
    }
    __syncthreads();

    // ---------------- GEMM1: 3 slices of 128 n (Q, K, V) -------------------
    const float scale = 0.17677669529663687f;  // 32^-0.5
#pragma unroll
    for (int s = 0; s < 3; s++) {
        if (warp < 8) {
            const int m2 = warp >> 2, n4 = warp & 3;
            const int r0 = m2 * 32 + g;        // rows r0, +8, +16, +24
            float acc[2][4][4];
#pragma unroll
            for (int m = 0; m < 2; m++)
#pragma unroll
                for (int t = 0; t < 4; t++)
                    acc[m][t][0] = acc[m][t][1] = acc[m][t][2] = acc[m][t][3] = 0.f;

#pragma unroll 4
            for (int kk = 0; kk < 16; kk++) {
                const int kc = kk * 8;
                float2 a00 = *(float2*)(XS + (r0)      * S136 + kc + tg2);
                float2 a01 = *(float2*)(XS + (r0 + 8)  * S136 + kc + tg2);
                float2 a10 = *(float2*)(XS + (r0 + 16) * S136 + kc + tg2);
                float2 a11 = *(float2*)(XS + (r0 + 24) * S136 + kc + tg2);
#pragma unroll
                for (int t = 0; t < 4; t++) {
                    float2 b = *(float2*)(WB + (n4 * 32 + t * 8 + g) * S136 + kc + tg2);
                    mma8(acc[0][t], a00.x, a01.x, a00.y, a01.y, b.x, b.y);
                    mma8(acc[1][t], a10.x, a11.x, a10.y, a11.y, b.x, b.y);
                }
            }
            // epilogue (slice: 0->Q, 1->K, 2->V^T)
#pragma unroll
            for (int m = 0; m < 2; m++) {
                const int rA = m2 * 32 + m * 16 + g, rB = rA + 8;
#pragma unroll
                for (int t = 0; t < 4; t++) {
                    const int c0 = n4 * 32 + t * 8 + tg2;       // 0..127
                    const float bb0 = qkv_b[s * 128 + c0];
                    const float bb1 = qkv_b[s * 128 + c0 + 1];
                    float v00 = acc[m][t][0] + bb0, v01 = acc[m][t][1] + bb1;
                    float v10 = acc[m][t][2] + bb0, v11 = acc[m][t][3] + bb1;
                    if (s == 0) {
                        Qb[rA * S136 + pk(c0)]     = tfs(v00 * scale);
                        Qb[rA * S136 + pk(c0 + 1)] = tfs(v01 * scale);
                        Qb[rB * S136 + pk(c0)]     = tfs(v10 * scale);
                        Qb[rB * S136 + pk(c0 + 1)] = tfs(v11 * scale);
                    } else if (s == 1) {
                        Kb[rA * S136 + pk(c0)]     = tfs(v00);
                        Kb[rA * S136 + pk(c0 + 1)] = tfs(v01);
                        Kb[rB * S136 + pk(c0)]     = tfs(v10);
                        Kb[rB * S136 + pk(c0 + 1)] = tfs(v11);
                    } else {
                        if (rA < NTOK) {
                            VT[c0 * SVT + pk(rA)]       = tfs(v00);
                            VT[(c0 + 1) * SVT + pk(rA)] = tfs(v01);
                        }
                        if (rB < NTOK) {
                            VT[c0 * SVT + pk(rB)]       = tfs(v10);
                            VT[(c0 + 1) * SVT + pk(rB)] = tfs(v11);
                        }
                    }
                }
            }
        } else if (s < 2) {
            // prefetch next slice to regs (768 threads, 4096 float4)
            const int t2 = tid - 256;
#pragma unroll
            for (int u = 0; u < 6; u++) {
                int idx = u * 768 + t2;
                if (idx < 4096) pfr[u] = wsrc[(s + 1) * 4096 + idx];
            }
        }
        __syncthreads();
        if (s < 2) {
            if (warp >= 8) {
                const int t2 = tid - 256;
#pragma unroll
                for (int u = 0; u < 6; u++) {
                    int idx = u * 768 + t2;
                    if (idx < 4096)
                        *(float4*)(WB + (idx >> 5) * S136 + (idx & 31) * 4) = pfr[u];
                }
            }
            __syncthreads();
        }
    }

    // ---------------- attention (warps 0-15) / proj prefetch (16-31) -------
    if (warp < 16) {
        const int h   = warp >> 2;
        const int mt2 = warp & 3;
        const int rb2 = mt2 * 16;
        float* Pw = WB + warp * (16 * SP);     // per-warp P scratch

        // GEMM2: logits [16][64] in regs
        float lv[8][4];
#pragma unroll
        for (int t = 0; t < 8; t++) lv[t][0] = lv[t][1] = lv[t][2] = lv[t][3] = 0.f;
#pragma unroll
        for (int kk = 0; kk < 4; kk++) {
            const int kc = h * 32 + kk * 8;
            float2 aA = *(float2*)(Qb + (rb2 + g)     * S136 + kc + tg2);
            float2 aB = *(float2*)(Qb + (rb2 + g + 8) * S136 + kc + tg2);
#pragma unroll
            for (int t = 0; t < 8; t++) {
                float2 b = *(float2*)(Kb + (t * 8 + g) * S136 + kc + tg2);
                mma8(lv[t], aA.x, aB.x, aA.y, aB.y, b.x, b.y);
            }
        }
        // + rpb+mask, softmax in regs
        {
            const int v = w % nmask;
            const float* rm0 = g_rm + ((size_t)((v * NHEAD + h) * 64 + rb2 + g)) * 64;
            const float* rm1 = rm0 + 8 * 64;
            float mx0 = -3.0e38f, mx1 = -3.0e38f;
#pragma unroll
            for (int t = 0; t < 8; t++) {
                const int j0 = t * 8 + tg2;
                float2 r0 = *(const float2*)(rm0 + j0);
                float2 r1 = *(const float2*)(rm1 + j0);
                lv[t][0] += r0.x; lv[t][1] += r0.y;
                lv[t][2] += r1.x; lv[t][3] += r1.y;
                mx0 = fmaxf(mx0, fmaxf(lv[t][0], lv[t][1]));
                mx1 = fmaxf(mx1, fmaxf(lv[t][2], lv[t][3]));
            }
            mx0 = fmaxf(mx0, __shfl_xor_sync(0xffffffffu, mx0, 1));
            mx0 = fmaxf(mx0, __shfl_xor_sync(0xffffffffu, mx0, 2));
            mx1 = fmaxf(mx1, __shfl_xor_sync(0xffffffffu, mx1, 1));
            mx1 = fmaxf(mx1, __shfl_xor_sync(0xffffffffu, mx1, 2));
            float s0 = 0.f, s1 = 0.f;
#pragma unroll
            for (int t = 0; t < 8; t++) {
                lv[t][0] = __expf(lv[t][0] - mx0);
                lv[t][1] = __expf(lv[t][1] - mx0);
                lv[t][2] = __expf(lv[t][2] - mx1);
                lv[t][3] = __expf(lv[t][3] - mx1);
                s0 += lv[t][0] + lv[t][1];
                s1 += lv[t][2] + lv[t][3];
            }
            s0 += __shfl_xor_sync(0xffffffffu, s0, 1);
            s0 += __shfl_xor_sync(0xffffffffu, s0, 2);
            s1 += __shfl_xor_sync(0xffffffffu, s1, 1);
            s1 += __shfl_xor_sync(0xffffffffu, s1, 2);
            const float inv0 = 1.0f / s0, inv1 = 1.0f / s1;

            // store unnormalized P (tf32), pk on token dim (tokens 0..55)
            const int pa = pk(tg2), pb = pk(tg2 + 1);
#pragma unroll
            for (int t = 0; t < 7; t++) {
                Pw[g * SP + t * 8 + pa]       = tfs(lv[t][0]);
                Pw[g * SP + t * 8 + pb]       = tfs(lv[t][1]);
                Pw[(g + 8) * SP + t * 8 + pa] = tfs(lv[t][2]);
                Pw[(g + 8) * SP + t * 8 + pb] = tfs(lv[t][3]);
            }
            __syncwarp();

            // GEMM3: ao [16][32] = P [16][56] @ V_h^T
            float a3[4][4];
#pragma unroll
            for (int t = 0; t < 4; t++) a3[t][0] = a3[t][1] = a3[t][2] = a3[t][3] = 0.f;
#pragma unroll
            for (int kk = 0; kk < 7; kk++) {
                const int kc = kk * 8;
                float2 aA = *(float2*)(Pw + g       * SP + kc + tg2);
                float2 aB = *(float2*)(Pw + (g + 8) * SP + kc + tg2);
#pragma unroll
                for (int t = 0; t < 4; t++) {
                    float2 b = *(float2*)(VT + (h * 32 + t * 8 + g) * SVT + kc + tg2);
                    mma8(a3[t], aA.x, aB.x, aA.y, aB.y, b.x, b.y);
                }
            }
            // normalize + store attn-out (packed A for GEMM4)
#pragma unroll
            for (int t = 0; t < 4; t++) {
                const int c0 = h * 32 + t * 8 + tg2;
                XS[(rb2 + g)     * S136 + pk(c0)]     = tfs(a3[t][0] * inv0);
                XS[(rb2 + g)     * S136 + pk(c0 + 1)] = tfs(a3[t][1] * inv0);
                XS[(rb2 + g + 8) * S136 + pk(c0)]     = tfs(a3[t][2] * inv1);
                XS[(rb2 + g + 8) * S136 + pk(c0 + 1)] = tfs(a3[t][3] * inv1);
            }
        }
    } else {
        const float4* psrc = (const float4*)g_wproj_t;
        const int t2 = tid - 512;
#pragma unroll
        for (int u = 0; u < 8; u++) pfr[u] = psrc[u * 512 + t2];
    }
    __syncthreads();

    if (warp >= 16) {
        const int t2 = tid - 512;
#pragma unroll
        for (int u = 0; u < 8; u++) {
            int idx = u * 512 + t2;
            *(float4*)(WB + (idx >> 5) * S136 + (idx & 31) * 4) = pfr[u];
        }
    }
    __syncthreads();

    // ---------------- GEMM4 (warps 0-7, 32x32 tiles), direct STG -----------
    if (warp < 8) {
        const int m2 = warp >> 2, n4 = warp & 3;
        const int r0 = m2 * 32 + g;
        float acc[2][4][4];
#pragma unroll
        for (int m = 0; m < 2; m++)
#pragma unroll
            for (int t = 0; t < 4; t++)
                acc[m][t][0] = acc[m][t][1] = acc[m][t][2] = acc[m][t][3] = 0.f;

#pragma unroll 4
        for (int kk = 0; kk < 16; kk++) {
            const int kc = kk * 8;
            float2 a00 = *(float2*)(XS + (r0)      * S136 + kc + tg2);
            float2 a01 = *(float2*)(XS + (r0 + 8)  * S136 + kc + tg2);
            float2 a10 = *(float2*)(XS + (r0 + 16) * S136 + kc + tg2);
            float2 a11 = *(float2*)(XS + (r0 + 24) * S136 + kc + tg2);
#pragma unroll
            for (int t = 0; t < 4; t++) {
                float2 b = *(float2*)(WB + (n4 * 32 + t * 8 + g) * S136 + kc + tg2);
                mma8(acc[0][t], a00.x, a01.x, a00.y, a01.y, b.x, b.y);
                mma8(acc[1][t], a10.x, a11.x, a10.y, a11.y, b.x, b.y);
            }
        }
        float* og = out + (size_t)w * NTOK * CDIM;
#pragma unroll
        for (int m = 0; m < 2; m++) {
            const int rA = m2 * 32 + m * 16 + g, rB = rA + 8;
#pragma unroll
            for (int t = 0; t < 4; t++) {
                const int c0 = n4 * 32 + t * 8 + tg2;
                const float b0 = proj_b[c0], b1 = proj_b[c0 + 1];
                if (rA < NTOK)
                    *(float2*)(og + rA * CDIM + c0) =
                        make_float2(acc[m][t][0] + b0, acc[m][t][1] + b1);
                if (rB < NTOK)
                    *(float2*)(og + rB * CDIM + c0) =
                        make_float2(acc[m][t][2] + b0, acc[m][t][3] + b1);
            }
        }
    }
}

extern "C" void kernel_launch(void* const* d_in, const int* in_sizes, int n_in,
                              void* d_out, int out_size) {
    const float* x      = (const float*)d_in[0];
    const float* qkv_w  = (const float*)d_in[1];
    const float* qkv_b  = (const float*)d_in[2];
    const float* proj_w = (const float*)d_in[3];
    const float* proj_b = (const float*)d_in[4];
    const float* bias_t = (const float*)d_in[5];
    const float* mask   = (const float*)d_in[6];
    float* out = (float*)d_out;

    const int bw    = in_sizes[0] / (NTOK * CDIM);   // 4096
    const int nmask = in_sizes[6] / (NTOK * NTOK);   // 64

    prepack_w<<<(TC3 * CDIM + CDIM * CDIM + 255) / 256, 256>>>(qkv_w, proj_w);
    {
        int total = nmask * NHEAD * 64 * 64;
        prepack_rm<<<(total + 255) / 256, 256>>>(mask, bias_t, nmask);
    }

    const size_t smem = SMEMF * sizeof(float);       // 215040 B
    cudaFuncSetAttribute(win_attn_kernel,
                         cudaFuncAttributeMaxDynamicSharedMemorySize, (int)smem);
    win_attn_kernel<<<bw, 1024, smem>>>(x, qkv_b, proj_b, out, nmask);
}

// round 8
// speedup vs baseline: 1.2390x; 1.2390x over previous
#include <cuda_runtime.h>
#include <cstdint>

// ---------------------------------------------------------------------------
// Swin WindowAttention, fused per-window TF32 mma.sync kernel, round 8.
// 512 threads (16 warps, 128 regs/thread -> spill-free).
// G1/G4: 16x32 warp tiles (1.5 LDS.64 per mma), register-prefetch staging.
// Attention: register softmax (R6), per-warp P scratch stride 68.
// ---------------------------------------------------------------------------

namespace {
constexpr int NTOK  = 49;
constexpr int CDIM  = 128;
constexpr int NHEAD = 4;
constexpr int TC3   = 384;
constexpr int MAXW  = 64;
constexpr int S136  = 136;   // operand stride (%32==8)
constexpr int SVT   = 72;    // V-transposed stride
constexpr int SP    = 68;    // per-warp P scratch stride (2g+tig uniform mod 16)

constexpr int OFF_XS = 0;                    // [64][136] x, then attn-out
constexpr int OFF_Q  = OFF_XS + 64 * S136;   // [64][136]
constexpr int OFF_K  = OFF_Q  + 64 * S136;   // [64][136]
constexpr int OFF_VT = OFF_K  + 64 * S136;   // [128][72]
constexpr int OFF_WB = OFF_VT + 128 * SVT;   // [128][136] W slice / P scratch
constexpr int SMEMF  = OFF_WB + 128 * S136;  // 52736 floats = 210944 B
}

__device__ float g_wqkv_t[TC3 * CDIM];             // [n=384][pk(k=128)]
__device__ float g_wproj_t[CDIM * CDIM];           // [n=128][pk(k=128)]
__device__ float g_rm[MAXW * NHEAD * 64 * 64];     // rpb+mask, padded with -1e30

__device__ __host__ __forceinline__ int pk(int c) {
    return (c & ~7) | ((c & 3) << 1) | ((c >> 2) & 1);
}

__device__ __forceinline__ float tfs(float f) {
    unsigned r;
    asm("cvt.rna.tf32.f32 %0, %1;" : "=r"(r) : "f"(f));
    return __uint_as_float(r);
}

__device__ __forceinline__ void mma8(float* c, float a0, float a1, float a2, float a3,
                                     float b0, float b1) {
    asm volatile(
        "mma.sync.aligned.m16n8k8.row.col.f32.tf32.tf32.f32 "
        "{%0,%1,%2,%3}, {%4,%5,%6,%7}, {%8,%9}, {%0,%1,%2,%3};"
        : "+f"(c[0]), "+f"(c[1]), "+f"(c[2]), "+f"(c[3])
        : "r"(__float_as_uint(a0)), "r"(__float_as_uint(a1)),
          "r"(__float_as_uint(a2)), "r"(__float_as_uint(a3)),
          "r"(__float_as_uint(b0)), "r"(__float_as_uint(b1)));
}

// ---------------- prepack kernels ------------------------------------------
__global__ void prepack_w(const float* __restrict__ qkv_w,
                          const float* __restrict__ proj_w) {
    int t = blockIdx.x * blockDim.x + threadIdx.x;
    if (t < TC3 * CDIM) {
        int n = t % TC3, k = t / TC3;
        g_wqkv_t[n * CDIM + pk(k)] = tfs(qkv_w[k * TC3 + n]);
    } else {
        int t2 = t - TC3 * CDIM;
        if (t2 < CDIM * CDIM) {
            int n = t2 % CDIM, k = t2 / CDIM;
            g_wproj_t[n * CDIM + pk(k)] = tfs(proj_w[k * CDIM + n]);
        }
    }
}

__global__ void prepack_rm(const float* __restrict__ mask,
                           const float* __restrict__ bias_t, int nmask) {
    int t = blockIdx.x * blockDim.x + threadIdx.x;
    int total = nmask * NHEAD * 64 * 64;
    if (t >= total) return;
    int j = t & 63;
    int i = (t >> 6) & 63;
    int h = (t >> 12) & (NHEAD - 1);
    int v = t >> 14;
    float val = -1.0e30f;
    if (i < NTOK && j < NTOK) {
        int ri = i / 7, ci = i - ri * 7;
        int rj = j / 7, cj = j - rj * 7;
        int idx = (ri - rj + 6) * 13 + (ci - cj + 6);
        val = bias_t[idx * NHEAD + h] + mask[(size_t)v * NTOK * NTOK + i * NTOK + j];
    }
    g_rm[t] = val;
}

// ---------------- main kernel ---------------------------------------------
__global__ __launch_bounds__(512, 1) void win_attn_kernel(
    const float* __restrict__ x,      const float* __restrict__ qkv_b,
    const float* __restrict__ proj_b, float* __restrict__ out, int nmask)
{
    extern __shared__ float sm[];
    float* XS = sm + OFF_XS;
    float* Qb = sm + OFF_Q;
    float* Kb = sm + OFF_K;
    float* VT = sm + OFF_VT;
    float* WB = sm + OFF_WB;

    const int w    = blockIdx.x;
    const int tid  = threadIdx.x;
    const int warp = tid >> 5;
    const int lane = tid & 31;
    const int g    = lane >> 2;
    const int tig  = lane & 3;
    const int tg2  = tig * 2;

    const int mt = warp & 3;         // M tile (16 rows)
    const int ng = warp >> 2;        // N group of 32 (0..3) for G1/G4
    const int rb = mt * 16;

    // ---------------- phase 0: stage x packed; zero pads --------------------
    {
        const float* xg = x + (size_t)w * NTOK * CDIM;
        // 49 rows x 16 groups of 8 floats = 784 tasks
        for (int u = tid; u < NTOK * 16; u += 512) {
            int r = u >> 4, gb = (u & 15) * 8;
            float4 v0 = *(const float4*)(xg + r * CDIM + gb);
            float4 v1 = *(const float4*)(xg + r * CDIM + gb + 4);
            float* d = XS + r * S136 + gb;
            *(float4*)(d)     = make_float4(tfs(v0.x), tfs(v1.x), tfs(v0.y), tfs(v1.y));
            *(float4*)(d + 4) = make_float4(tfs(v0.z), tfs(v1.z), tfs(v0.w), tfs(v1.w));
        }
        for (int u = tid; u < 15 * S136; u += 512)       // XS pad rows = 0
            XS[NTOK * S136 + u] = 0.0f;
        for (int u = tid; u < CDIM * 8; u += 512) {      // VT pad tokens 48..55 = 0
            int ch = u >> 3, t = 48 + (u & 7);
            VT[ch * SVT + pk(t)] = 0.0f;                 // t=48 overwritten later
        }
    }

    const float4* wsrc = (const float4*)g_wqkv_t;
    float4 pf[8];
    // prefetch slice 0 (4096 float4 / 512 thr = 8 each)
#pragma unroll
    for (int u = 0; u < 8; u++) pf[u] = wsrc[u * 512 + tid];
    __syncthreads();                                     // (1) phase0 done
#pragma unroll
    for (int u = 0; u < 8; u++) {
        int idx = u * 512 + tid;
        *(float4*)(WB + (idx >> 5) * S136 + (idx & 31) * 4) = pf[u];
    }
    __syncthreads();                                     // (2) slice 0 staged

    // ---------------- GEMM1: 3 slices of 128 n (Q, K, V) -------------------
    const float scale = 0.17677669529663687f;  // 32^-0.5
#pragma unroll
    for (int s = 0; s < 3; s++) {
        if (s < 2) {
#pragma unroll
            for (int u = 0; u < 8; u++) pf[u] = wsrc[(s + 1) * 4096 + u * 512 + tid];
        }
        float acc[4][4];
#pragma unroll
        for (int t = 0; t < 4; t++) acc[t][0] = acc[t][1] = acc[t][2] = acc[t][3] = 0.f;

#pragma unroll 4
        for (int kk = 0; kk < 16; kk++) {
            const int kc = kk * 8;
            float2 aA = *(float2*)(XS + (rb + g)     * S136 + kc + tg2);
            float2 aB = *(float2*)(XS + (rb + g + 8) * S136 + kc + tg2);
#pragma unroll
            for (int t = 0; t < 4; t++) {
                float2 b = *(float2*)(WB + (ng * 32 + t * 8 + g) * S136 + kc + tg2);
                mma8(acc[t], aA.x, aB.x, aA.y, aB.y, b.x, b.y);
            }
        }
        // epilogue (slice: 0->Q, 1->K, 2->V^T)
        const int r0 = rb + g, r1 = rb + g + 8;
#pragma unroll
        for (int t = 0; t < 4; t++) {
            const int c0 = ng * 32 + t * 8 + tg2;        // 0..127
            const float bb0 = qkv_b[s * 128 + c0], bb1 = qkv_b[s * 128 + c0 + 1];
            float v00 = acc[t][0] + bb0, v01 = acc[t][1] + bb1;
            float v10 = acc[t][2] + bb0, v11 = acc[t][3] + bb1;
            if (s == 0) {
                Qb[r0 * S136 + pk(c0)]     = tfs(v00 * scale);
                Qb[r0 * S136 + pk(c0 + 1)] = tfs(v01 * scale);
                Qb[r1 * S136 + pk(c0)]     = tfs(v10 * scale);
                Qb[r1 * S136 + pk(c0 + 1)] = tfs(v11 * scale);
            } else if (s == 1) {
                Kb[r0 * S136 + pk(c0)]     = tfs(v00);
                Kb[r0 * S136 + pk(c0 + 1)] = tfs(v01);
                Kb[r1 * S136 + pk(c0)]     = tfs(v10);
                Kb[r1 * S136 + pk(c0 + 1)] = tfs(v11);
            } else {
                if (r0 < NTOK) {
                    VT[c0 * SVT + pk(r0)]       = tfs(v00);
                    VT[(c0 + 1) * SVT + pk(r0)] = tfs(v01);
                }
                if (r1 < NTOK) {
                    VT[c0 * SVT + pk(r1)]       = tfs(v10);
                    VT[(c0 + 1) * SVT + pk(r1)] = tfs(v11);
                }
            }
        }
        __syncthreads();                                 // compute done
        if (s < 2) {
#pragma unroll
            for (int u = 0; u < 8; u++) {
                int idx = u * 512 + tid;
                *(float4*)(WB + (idx >> 5) * S136 + (idx & 31) * 4) = pf[u];
            }
            __syncthreads();                             // next slice staged
        }
    }

    // ---------------- attention: 16 warps = (head, m-tile) ------------------
    {
        const int h   = warp >> 2;
        const int mt2 = warp & 3;
        const int rb2 = mt2 * 16;
        float* Pw = WB + warp * (16 * SP);   // per-warp P scratch (WB free now)

        // GEMM2: logits [16][64] in regs
        float lv[8][4];
#pragma unroll
        for (int t = 0; t < 8; t++) lv[t][0] = lv[t][1] = lv[t][2] = lv[t][3] = 0.f;
#pragma unroll
        for (int kk = 0; kk < 4; kk++) {
            const int kc = h * 32 + kk * 8;
            float2 aA = *(float2*)(Qb + (rb2 + g)     * S136 + kc + tg2);
            float2 aB = *(float2*)(Qb + (rb2 + g + 8) * S136 + kc + tg2);
#pragma unroll
            for (int t = 0; t < 8; t++) {
                float2 b = *(float2*)(Kb + (t * 8 + g) * S136 + kc + tg2);
                mma8(lv[t], aA.x, aB.x, aA.y, aB.y, b.x, b.y);
            }
        }
        // + rpb+mask (padded table), softmax in regs
        const int v = w % nmask;
        const float* rm0 = g_rm + ((size_t)((v * NHEAD + h) * 64 + rb2 + g)) * 64;
        const float* rm1 = rm0 + 8 * 64;
        float mx0 = -3.0e38f, mx1 = -3.0e38f;
#pragma unroll
        for (int t = 0; t < 8; t++) {
            const int j0 = t * 8 + tg2;
            float2 r0 = *(const float2*)(rm0 + j0);
            float2 r1 = *(const float2*)(rm1 + j0);
            lv[t][0] += r0.x; lv[t][1] += r0.y;
            lv[t][2] += r1.x; lv[t][3] += r1.y;
            mx0 = fmaxf(mx0, fmaxf(lv[t][0], lv[t][1]));
            mx1 = fmaxf(mx1, fmaxf(lv[t][2], lv[t][3]));
        }
        mx0 = fmaxf(mx0, __shfl_xor_sync(0xffffffffu, mx0, 1));
        mx0 = fmaxf(mx0, __shfl_xor_sync(0xffffffffu, mx0, 2));
        mx1 = fmaxf(mx1, __shfl_xor_sync(0xffffffffu, mx1, 1));
        mx1 = fmaxf(mx1, __shfl_xor_sync(0xffffffffu, mx1, 2));
        float s0 = 0.f, s1 = 0.f;
#pragma unroll
        for (int t = 0; t < 8; t++) {
            lv[t][0] = __expf(lv[t][0] - mx0);
            lv[t][1] = __expf(lv[t][1] - mx0);
            lv[t][2] = __expf(lv[t][2] - mx1);
            lv[t][3] = __expf(lv[t][3] - mx1);
            s0 += lv[t][0] + lv[t][1];
            s1 += lv[t][2] + lv[t][3];
        }
        s0 += __shfl_xor_sync(0xffffffffu, s0, 1);
        s0 += __shfl_xor_sync(0xffffffffu, s0, 2);
        s1 += __shfl_xor_sync(0xffffffffu, s1, 1);
        s1 += __shfl_xor_sync(0xffffffffu, s1, 2);
        const float inv0 = 1.0f / s0, inv1 = 1.0f / s1;

        // store unnormalized P (tf32), pk on token dim (tokens 0..55)
        const int pa = pk(tg2), pb = pk(tg2 + 1);
#pragma unroll
        for (int t = 0; t < 7; t++) {
            Pw[g * SP + t * 8 + pa]       = tfs(lv[t][0]);
            Pw[g * SP + t * 8 + pb]       = tfs(lv[t][1]);
            Pw[(g + 8) * SP + t * 8 + pa] = tfs(lv[t][2]);
            Pw[(g + 8) * SP + t * 8 + pb] = tfs(lv[t][3]);
        }
        __syncwarp();

        // GEMM3: ao [16][32] = P [16][56] @ V_h^T
        float a3[4][4];
#pragma unroll
        for (int t = 0; t < 4; t++) a3[t][0] = a3[t][1] = a3[t][2] = a3[t][3] = 0.f;
#pragma unroll
        for (int kk = 0; kk < 7; kk++) {
            const int kc = kk * 8;
            float2 aA = *(float2*)(Pw + g       * SP + kc + tg2);
            float2 aB = *(float2*)(Pw + (g + 8) * SP + kc + tg2);
#pragma unroll
            for (int t = 0; t < 4; t++) {
                float2 b = *(float2*)(VT + (h * 32 + t * 8 + g) * SVT + kc + tg2);
                mma8(a3[t], aA.x, aB.x, aA.y, aB.y, b.x, b.y);
            }
        }
        // normalize + store attn-out (packed A for GEMM4)
#pragma unroll
        for (int t = 0; t < 4; t++) {
            const int c0 = h * 32 + t * 8 + tg2;
            XS[(rb2 + g)     * S136 + pk(c0)]     = tfs(a3[t][0] * inv0);
            XS[(rb2 + g)     * S136 + pk(c0 + 1)] = tfs(a3[t][1] * inv0);
            XS[(rb2 + g + 8) * S136 + pk(c0)]     = tfs(a3[t][2] * inv1);
            XS[(rb2 + g + 8) * S136 + pk(c0 + 1)] = tfs(a3[t][3] * inv1);
        }
    }
    __syncthreads();                                     // attention done

    // ---------------- stage proj_w into WB ---------------------------------
    {
        const float4* psrc = (const float4*)g_wproj_t;
#pragma unroll
        for (int u = 0; u < 8; u++) pf[u] = psrc[u * 512 + tid];
#pragma unroll
        for (int u = 0; u < 8; u++) {
            int idx = u * 512 + tid;
            *(float4*)(WB + (idx >> 5) * S136 + (idx & 31) * 4) = pf[u];
        }
    }
    __syncthreads();                                     // proj staged

    // ---------------- GEMM4: y[64,128] = ao @ proj_w + b, direct STG -------
    {
        float acc[4][4];
#pragma unroll
        for (int t = 0; t < 4; t++) acc[t][0] = acc[t][1] = acc[t][2] = acc[t][3] = 0.f;
#pragma unroll 4
        for (int kk = 0; kk < 16; kk++) {
            const int kc = kk * 8;
            float2 aA = *(float2*)(XS + (rb + g)     * S136 + kc + tg2);
            float2 aB = *(float2*)(XS + (rb + g + 8) * S136 + kc + tg2);
#pragma unroll
            for (int t = 0; t < 4; t++) {
                float2 b = *(float2*)(WB + (ng * 32 + t * 8 + g) * S136 + kc + tg2);
                mma8(acc[t], aA.x, aB.x, aA.y, aB.y, b.x, b.y);
            }
        }
        float* og = out + (size_t)w * NTOK * CDIM;
        const int r0 = rb + g, r1 = rb + g + 8;
#pragma unroll
        for (int t = 0; t < 4; t++) {
            const int c0 = ng * 32 + t * 8 + tg2;
            const float b0 = proj_b[c0], b1 = proj_b[c0 + 1];
            if (r0 < NTOK)
                *(float2*)(og + r0 * CDIM + c0) = make_float2(acc[t][0] + b0, acc[t][1] + b1);
            if (r1 < NTOK)
                *(float2*)(og + r1 * CDIM + c0) = make_float2(acc[t][2] + b0, acc[t][3] + b1);
        }
    }
}

extern "C" void kernel_launch(void* const* d_in, const int* in_sizes, int n_in,
                              void* d_out, int out_size) {
    const float* x      = (const float*)d_in[0];
    const float* qkv_w  = (const float*)d_in[1];
    const float* qkv_b  = (const float*)d_in[2];
    const float* proj_w = (const float*)d_in[3];
    const float* proj_b = (const float*)d_in[4];
    const float* bias_t = (const float*)d_in[5];
    const float* mask   = (const float*)d_in[6];
    float* out = (float*)d_out;

    const int bw    = in_sizes[0] / (NTOK * CDIM);   // 4096
    const int nmask = in_sizes[6] / (NTOK * NTOK);   // 64

    prepack_w<<<(TC3 * CDIM + CDIM * CDIM + 255) / 256, 256>>>(qkv_w, proj_w);
    {
        int total = nmask * NHEAD * 64 * 64;
        prepack_rm<<<(total + 255) / 256, 256>>>(mask, bias_t, nmask);
    }

    const size_t smem = SMEMF * sizeof(float);       // 210944 B
    cudaFuncSetAttribute(win_attn_kernel,
                         cudaFuncAttributeMaxDynamicSharedMemorySize, (int)smem);
    win_attn_kernel<<<bw, 512, smem>>>(x, qkv_b, proj_b, out, nmask);
}

// round 9
// speedup vs baseline: 2.0491x; 1.6538x over previous
#include <cuda_runtime.h>
#include <cuda_fp16.h>
#include <cstdint>

// ---------------------------------------------------------------------------
// Swin WindowAttention, fused per-window FP16 mma.sync kernel (m16n8k16),
// round 9. 512 threads, 128 regs (spill-free). fp16 operands + fp32 accum
// (same 10-bit mantissa as tf32). pk16-interleaved smem so one LDS.64 feeds
// a full A/B k16 fragment half. P stays in registers (C->A fragment match).
// ---------------------------------------------------------------------------

namespace {
constexpr int NTOK  = 49;
constexpr int CDIM  = 128;
constexpr int NHEAD = 4;
constexpr int TC3   = 384;
constexpr int MAXW  = 64;
constexpr int S144  = 144;   // fp16-unit stride, %64==16 -> conflict-free 8B LDS
constexpr int SVT   = 80;    // VT stride (k=64 tokens), %64==16

constexpr int OFF_XS = 0;                    // [64][144] x, then attn-out
constexpr int OFF_Q  = OFF_XS + 64 * S144;   // 9216
constexpr int OFF_K  = OFF_Q  + 64 * S144;   // 18432
constexpr int OFF_VT = OFF_K  + 64 * S144;   // 27648  [128][80]
constexpr int OFF_WB = OFF_VT + 128 * SVT;   // 37888  [128][144] W slice
constexpr int SMEMH  = OFF_WB + 128 * S144;  // 56320 halfs = 112640 B
}

__device__ __half g_wqkv_h[TC3 * CDIM];            // [n=384][pk16(k=128)]
__device__ __half g_wproj_h[CDIM * CDIM];          // [n=128][pk16(k=128)]
__device__ float  g_rm[MAXW * NHEAD * 64 * 64];    // rpb+mask, padded -1e30

// k-interleave within each 16-group: storage order [0,1,8,9,2,3,10,11,...]
// so 4 consecutive halfs at offset 4t = k{2t,2t+1,2t+8,2t+9} = one frag half.
__device__ __forceinline__ int pk16(int k) {
    return (k & ~15) | (((k >> 1) & 3) << 2) | ((k & 8) >> 2) | (k & 1);
}

__device__ __forceinline__ uint32_t h2u(float a, float b) {
    __half2 h = __floats2half2_rn(a, b);
    return *reinterpret_cast<uint32_t*>(&h);
}

// m16n8k16 fp16 mma, fp32 accum. alo = row g (a0,a2), ahi = row g+8 (a1,a3).
__device__ __forceinline__ void mma16(float* c, uint2 alo, uint2 ahi, uint2 b) {
    asm volatile(
        "mma.sync.aligned.m16n8k16.row.col.f32.f16.f16.f32 "
        "{%0,%1,%2,%3}, {%4,%5,%6,%7}, {%8,%9}, {%0,%1,%2,%3};"
        : "+f"(c[0]), "+f"(c[1]), "+f"(c[2]), "+f"(c[3])
        : "r"(alo.x), "r"(ahi.x), "r"(alo.y), "r"(ahi.y), "r"(b.x), "r"(b.y));
}

// ---------------- prepack kernels ------------------------------------------
__global__ void prepack_w(const float* __restrict__ qkv_w,
                          const float* __restrict__ proj_w) {
    int t = blockIdx.x * blockDim.x + threadIdx.x;
    if (t < TC3 * CDIM) {
        int n = t % TC3, k = t / TC3;
        g_wqkv_h[n * CDIM + pk16(k)] = __float2half_rn(qkv_w[k * TC3 + n]);
    } else {
        int t2 = t - TC3 * CDIM;
        if (t2 < CDIM * CDIM) {
            int n = t2 % CDIM, k = t2 / CDIM;
            g_wproj_h[n * CDIM + pk16(k)] = __float2half_rn(proj_w[k * CDIM + n]);
        }
    }
}

__global__ void prepack_rm(const float* __restrict__ mask,
                           const float* __restrict__ bias_t, int nmask) {
    int t = blockIdx.x * blockDim.x + threadIdx.x;
    int total = nmask * NHEAD * 64 * 64;
    if (t >= total) return;
    int j = t & 63;
    int i = (t >> 6) & 63;
    int h = (t >> 12) & (NHEAD - 1);
    int v = t >> 14;
    float val = -1.0e30f;
    if (i < NTOK && j < NTOK) {
        int ri = i / 7, ci = i - ri * 7;
        int rj = j / 7, cj = j - rj * 7;
        int idx = (ri - rj + 6) * 13 + (ci - cj + 6);
        val = bias_t[idx * NHEAD + h] + mask[(size_t)v * NTOK * NTOK + i * NTOK + j];
    }
    g_rm[t] = val;
}

// ---------------- main kernel ---------------------------------------------
__global__ __launch_bounds__(512, 1) void win_attn_kernel(
    const float* __restrict__ x,      const float* __restrict__ qkv_b,
    const float* __restrict__ proj_b, float* __restrict__ out, int nmask)
{
    extern __shared__ __half smh[];
    __half* XS = smh + OFF_XS;
    __half* Qb = smh + OFF_Q;
    __half* Kb = smh + OFF_K;
    __half* VT = smh + OFF_VT;
    __half* WB = smh + OFF_WB;

    const int w    = blockIdx.x;
    const int tid  = threadIdx.x;
    const int warp = tid >> 5;
    const int lane = tid & 31;
    const int g    = lane >> 2;
    const int tig  = lane & 3;
    const int t4   = tig * 4;        // frag offset within k16 group

    const int mt = warp & 3;         // M tile (16 rows) for G1/G4
    const int ng = warp >> 2;        // N group of 32 for G1/G4
    const int rb = mt * 16;

    // ---------------- phase 0: stage x (fp16, pk16); zero pads --------------
    {
        const float* xg = x + (size_t)w * NTOK * CDIM;
        if (tid < NTOK * 8) {                         // 49 rows x 8 groups of 16ch
            int r = tid >> 3, cb = (tid & 7) * 16;
            const float4* xr = (const float4*)(xg + r * CDIM + cb);
            float4 f0 = xr[0], f1 = xr[1], f2 = xr[2], f3 = xr[3];
            uint4 lo, hi;
            lo.x = h2u(f0.x, f0.y);  lo.y = h2u(f2.x, f2.y);   // ch 0,1 | 8,9
            lo.z = h2u(f0.z, f0.w);  lo.w = h2u(f2.z, f2.w);   // ch 2,3 | 10,11
            hi.x = h2u(f1.x, f1.y);  hi.y = h2u(f3.x, f3.y);   // ch 4,5 | 12,13
            hi.z = h2u(f1.z, f1.w);  hi.w = h2u(f3.z, f3.w);   // ch 6,7 | 14,15
            uint4* d = (uint4*)(XS + r * S144 + cb);
            d[0] = lo; d[1] = hi;
        }
        if (tid < 270) {                              // XS pad rows 49..63 = 0
            uint4 z = {0, 0, 0, 0};
            *(uint4*)(XS + NTOK * S144 + tid * 8) = z;
        }
        for (int u = tid; u < 1280; u += 512) {       // zero whole VT
            uint4 z = {0, 0, 0, 0};
            *(uint4*)(VT + u * 8) = z;
        }
    }

    const uint4* wsrc = (const uint4*)g_wqkv_h;       // 2048 uint4 per slice
    uint4 pf[4];
#pragma unroll
    for (int u = 0; u < 4; u++) pf[u] = wsrc[u * 512 + tid];
    __syncthreads();                                  // (1) phase0 done
#pragma unroll
    for (int u = 0; u < 4; u++) {
        int idx = u * 512 + tid;
        *(uint4*)(WB + (idx >> 4) * S144 + (idx & 15) * 8) = pf[u];
    }
    __syncthreads();                                  // (2) slice 0 staged

    // ---------------- GEMM1: 3 slices of 128 n (Q, K, V) -------------------
    const float scale = 0.17677669529663687f;  // 32^-0.5
#pragma unroll
    for (int s = 0; s < 3; s++) {
        if (s < 2) {
#pragma unroll
            for (int u = 0; u < 4; u++) pf[u] = wsrc[(s + 1) * 2048 + u * 512 + tid];
        }
        float acc[4][4];
#pragma unroll
        for (int t = 0; t < 4; t++) acc[t][0] = acc[t][1] = acc[t][2] = acc[t][3] = 0.f;

#pragma unroll
        for (int kk = 0; kk < 8; kk++) {
            const int kc = kk * 16;
            uint2 aA = *(uint2*)(XS + (rb + g)     * S144 + kc + t4);
            uint2 aB = *(uint2*)(XS + (rb + g + 8) * S144 + kc + t4);
#pragma unroll
            for (int t = 0; t < 4; t++) {
                uint2 b = *(uint2*)(WB + (ng * 32 + t * 8 + g) * S144 + kc + t4);
                mma16(acc[t], aA, aB, b);
            }
        }
        // epilogue (slice: 0->Q, 1->K, 2->V^T)
        const int r0 = rb + g, r1 = rb + g + 8;
#pragma unroll
        for (int t = 0; t < 4; t++) {
            const int c0 = ng * 32 + t * 8 + 2 * tig;     // even, 0..126
            const int po = pk16(c0);                      // even
            const float bb0 = qkv_b[s * 128 + c0], bb1 = qkv_b[s * 128 + c0 + 1];
            float v00 = acc[t][0] + bb0, v01 = acc[t][1] + bb1;
            float v10 = acc[t][2] + bb0, v11 = acc[t][3] + bb1;
            if (s == 0) {
                *(__half2*)(Qb + r0 * S144 + po) = __floats2half2_rn(v00 * scale, v01 * scale);
                *(__half2*)(Qb + r1 * S144 + po) = __floats2half2_rn(v10 * scale, v11 * scale);
            } else if (s == 1) {
                *(__half2*)(Kb + r0 * S144 + po) = __floats2half2_rn(v00, v01);
                *(__half2*)(Kb + r1 * S144 + po) = __floats2half2_rn(v10, v11);
            } else {
                if (r0 < NTOK) {
                    VT[c0 * SVT + pk16(r0)]       = __float2half_rn(v00);
                    VT[(c0 + 1) * SVT + pk16(r0)] = __float2half_rn(v01);
                }
                if (r1 < NTOK) {
                    VT[c0 * SVT + pk16(r1)]       = __float2half_rn(v10);
                    VT[(c0 + 1) * SVT + pk16(r1)] = __float2half_rn(v11);
                }
            }
        }
        __syncthreads();                              // slice consumed
        if (s < 2) {
#pragma unroll
            for (int u = 0; u < 4; u++) {
                int idx = u * 512 + tid;
                *(uint4*)(WB + (idx >> 4) * S144 + (idx & 15) * 8) = pf[u];
            }
            __syncthreads();                          // next slice staged
        }
    }

    // prefetch proj_w to regs (STS after attention; WB unused until G4)
    {
        const uint4* psrc = (const uint4*)g_wproj_h;
#pragma unroll
        for (int u = 0; u < 4; u++) pf[u] = psrc[u * 512 + tid];
    }

    // ---------------- attention: warp = (head, m-tile), no smem P -----------
    {
        const int h   = warp >> 2;
        const int mt2 = warp & 3;
        const int rb2 = mt2 * 16;

        // GEMM2: logits [16][64] in regs (k = 32 = 2 k16 steps)
        float lv[8][4];
#pragma unroll
        for (int t = 0; t < 8; t++) lv[t][0] = lv[t][1] = lv[t][2] = lv[t][3] = 0.f;
#pragma unroll
        for (int kk = 0; kk < 2; kk++) {
            const int kc = h * 32 + kk * 16;
            uint2 aA = *(uint2*)(Qb + (rb2 + g)     * S144 + kc + t4);
            uint2 aB = *(uint2*)(Qb + (rb2 + g + 8) * S144 + kc + t4);
#pragma unroll
            for (int t = 0; t < 8; t++) {
                uint2 b = *(uint2*)(Kb + (t * 8 + g) * S144 + kc + t4);
                mma16(lv[t], aA, aB, b);
            }
        }
        // + rpb+mask, softmax in regs
        const int v = w % nmask;
        const float* rm0 = g_rm + ((size_t)((v * NHEAD + h) * 64 + rb2 + g)) * 64;
        const float* rm1 = rm0 + 8 * 64;
        float mx0 = -3.0e38f, mx1 = -3.0e38f;
#pragma unroll
        for (int t = 0; t < 8; t++) {
            const int j0 = t * 8 + 2 * tig;
            float2 r0 = *(const float2*)(rm0 + j0);
            float2 r1 = *(const float2*)(rm1 + j0);
            lv[t][0] += r0.x; lv[t][1] += r0.y;
            lv[t][2] += r1.x; lv[t][3] += r1.y;
            mx0 = fmaxf(mx0, fmaxf(lv[t][0], lv[t][1]));
            mx1 = fmaxf(mx1, fmaxf(lv[t][2], lv[t][3]));
        }
        mx0 = fmaxf(mx0, __shfl_xor_sync(0xffffffffu, mx0, 1));
        mx0 = fmaxf(mx0, __shfl_xor_sync(0xffffffffu, mx0, 2));
        mx1 = fmaxf(mx1, __shfl_xor_sync(0xffffffffu, mx1, 1));
        mx1 = fmaxf(mx1, __shfl_xor_sync(0xffffffffu, mx1, 2));
        float s0 = 0.f, s1 = 0.f;
#pragma unroll
        for (int t = 0; t < 8; t++) {
            lv[t][0] = __expf(lv[t][0] - mx0);
            lv[t][1] = __expf(lv[t][1] - mx0);
            lv[t][2] = __expf(lv[t][2] - mx1);
            lv[t][3] = __expf(lv[t][3] - mx1);
            s0 += lv[t][0] + lv[t][1];
            s1 += lv[t][2] + lv[t][3];
        }
        s0 += __shfl_xor_sync(0xffffffffu, s0, 1);
        s0 += __shfl_xor_sync(0xffffffffu, s0, 2);
        s1 += __shfl_xor_sync(0xffffffffu, s1, 1);
        s1 += __shfl_xor_sync(0xffffffffu, s1, 2);
        const float inv0 = 1.0f / s0, inv1 = 1.0f / s1;

        // GEMM3: ao [16][32] = P [16][64] @ V_h^T; P built from lv regs:
        // logits C-fragment layout == fp16 A-fragment layout (c0,c1 -> a0).
        float a3[4][4];
#pragma unroll
        for (int t = 0; t < 4; t++) a3[t][0] = a3[t][1] = a3[t][2] = a3[t][3] = 0.f;
#pragma unroll
        for (int kk = 0; kk < 4; kk++) {
            uint2 alo, ahi;
            alo.x = h2u(lv[2 * kk][0],     lv[2 * kk][1]);      // a0: row g,   k 2t,2t+1
            alo.y = h2u(lv[2 * kk + 1][0], lv[2 * kk + 1][1]);  // a2: row g,   k +8
            ahi.x = h2u(lv[2 * kk][2],     lv[2 * kk][3]);      // a1: row g+8
            ahi.y = h2u(lv[2 * kk + 1][2], lv[2 * kk + 1][3]);  // a3: row g+8, +8
#pragma unroll
            for (int t = 0; t < 4; t++) {
                uint2 b = *(uint2*)(VT + (h * 32 + t * 8 + g) * SVT + kk * 16 + t4);
                mma16(a3[t], alo, ahi, b);
            }
        }
        // normalize + store attn-out (fp16 packed A for GEMM4)
#pragma unroll
        for (int t = 0; t < 4; t++) {
            const int c0 = h * 32 + t * 8 + 2 * tig;
            const int po = pk16(c0);
            *(__half2*)(XS + (rb2 + g)     * S144 + po) =
                __floats2half2_rn(a3[t][0] * inv0, a3[t][1] * inv0);
            *(__half2*)(XS + (rb2 + g + 8) * S144 + po) =
                __floats2half2_rn(a3[t][2] * inv1, a3[t][3] * inv1);
        }
    }
    // stage proj_w from regs
#pragma unroll
    for (int u = 0; u < 4; u++) {
        int idx = u * 512 + tid;
        *(uint4*)(WB + (idx >> 4) * S144 + (idx & 15) * 8) = pf[u];
    }
    __syncthreads();                                  // attn-out + proj staged

    // ---------------- GEMM4: y[64,128] = ao @ proj_w + b, direct STG -------
    {
        float acc[4][4];
#pragma unroll
        for (int t = 0; t < 4; t++) acc[t][0] = acc[t][1] = acc[t][2] = acc[t][3] = 0.f;
#pragma unroll
        for (int kk = 0; kk < 8; kk++) {
            const int kc = kk * 16;
            uint2 aA = *(uint2*)(XS + (rb + g)     * S144 + kc + t4);
            uint2 aB = *(uint2*)(XS + (rb + g + 8) * S144 + kc + t4);
#pragma unroll
            for (int t = 0; t < 4; t++) {
                uint2 b = *(uint2*)(WB + (ng * 32 + t * 8 + g) * S144 + kc + t4);
                mma16(acc[t], aA, aB, b);
            }
        }
        float* og = out + (size_t)w * NTOK * CDIM;
        const int r0 = rb + g, r1 = rb + g + 8;
#pragma unroll
        for (int t = 0; t < 4; t++) {
            const int c0 = ng * 32 + t * 8 + 2 * tig;
            const float b0 = proj_b[c0], b1 = proj_b[c0 + 1];
            if (r0 < NTOK)
                *(float2*)(og + r0 * CDIM + c0) = make_float2(acc[t][0] + b0, acc[t][1] + b1);
            if (r1 < NTOK)
                *(float2*)(og + r1 * CDIM + c0) = make_float2(acc[t][2] + b0, acc[t][3] + b1);
        }
    }
}

extern "C" void kernel_launch(void* const* d_in, const int* in_sizes, int n_in,
                              void* d_out, int out_size) {
    const float* x      = (const float*)d_in[0];
    const float* qkv_w  = (const float*)d_in[1];
    const float* qkv_b  = (const float*)d_in[2];
    const float* proj_w = (const float*)d_in[3];
    const float* proj_b = (const float*)d_in[4];
    const float* bias_t = (const float*)d_in[5];
    const float* mask   = (const float*)d_in[6];
    float* out = (float*)d_out;

    const int bw    = in_sizes[0] / (NTOK * CDIM);   // 4096
    const int nmask = in_sizes[6] / (NTOK * NTOK);   // 64

    prepack_w<<<(TC3 * CDIM + CDIM * CDIM + 255) / 256, 256>>>(qkv_w, proj_w);
    {
        int total = nmask * NHEAD * 64 * 64;
        prepack_rm<<<(total + 255) / 256, 256>>>(mask, bias_t, nmask);
    }

    const size_t smem = SMEMH * sizeof(__half);      // 112640 B
    cudaFuncSetAttribute(win_attn_kernel,
                         cudaFuncAttributeMaxDynamicSharedMemorySize, (int)smem);
    win_attn_kernel<<<bw, 512, smem>>>(x, qkv_b, proj_b, out, nmask);
}

// round 10
// speedup vs baseline: 2.4414x; 1.1915x over previous
#include <cuda_runtime.h>
#include <cuda_fp16.h>
#include <cstdint>

// ---------------------------------------------------------------------------
// Swin WindowAttention, fused FP16 mma.sync kernel (m16n8k16), round 10.
// 2 windows per CTA (M=128): weight LDG/STS + barriers amortized, 32x32
// warp tiles in G1/G4 (1.0 LDS.64 per mma). 512 threads, spill-free.
// ---------------------------------------------------------------------------

namespace {
constexpr int NTOK  = 49;
constexpr int CDIM  = 128;
constexpr int NHEAD = 4;
constexpr int TC3   = 384;
constexpr int MAXW  = 64;
constexpr int S     = 144;   // fp16-unit stride (288 B), conflict-free

constexpr int OFF_XS = 0;            // [128][144] x (2 windows), then attn-out
constexpr int OFF_Q  = 128 * S;      // [128][144]
constexpr int OFF_K  = 2 * 128 * S;  // [128][144]
constexpr int OFF_VT = 3 * 128 * S;  // [128][144]  V^T: [ch][win*64 + pk16(tok)]
constexpr int OFF_WB = 4 * 128 * S;  // [128][144]  W slice
constexpr int SMEMH  = 5 * 128 * S;  // 92160 halfs = 184320 B
}

__device__ __half g_wqkv_h[TC3 * CDIM];            // [n=384][pk16(k=128)]
__device__ __half g_wproj_h[CDIM * CDIM];          // [n=128][pk16(k=128)]
__device__ float  g_rm[MAXW * NHEAD * 64 * 64];    // rpb+mask, padded -1e30

// k-interleave within each 16-group: 4 consecutive halfs at 4t = k{2t,2t+1,2t+8,2t+9}
__device__ __forceinline__ int pk16(int k) {
    return (k & ~15) | (((k >> 1) & 3) << 2) | ((k & 8) >> 2) | (k & 1);
}

__device__ __forceinline__ uint32_t h2u(float a, float b) {
    __half2 h = __floats2half2_rn(a, b);
    return *reinterpret_cast<uint32_t*>(&h);
}

__device__ __forceinline__ void mma16(float* c, uint2 alo, uint2 ahi, uint2 b) {
    asm volatile(
        "mma.sync.aligned.m16n8k16.row.col.f32.f16.f16.f32 "
        "{%0,%1,%2,%3}, {%4,%5,%6,%7}, {%8,%9}, {%0,%1,%2,%3};"
        : "+f"(c[0]), "+f"(c[1]), "+f"(c[2]), "+f"(c[3])
        : "r"(alo.x), "r"(ahi.x), "r"(alo.y), "r"(ahi.y), "r"(b.x), "r"(b.y));
}

// ---------------- prepack kernels ------------------------------------------
__global__ void prepack_w(const float* __restrict__ qkv_w,
                          const float* __restrict__ proj_w) {
    int t = blockIdx.x * blockDim.x + threadIdx.x;
    if (t < TC3 * CDIM) {
        int n = t % TC3, k = t / TC3;
        g_wqkv_h[n * CDIM + pk16(k)] = __float2half_rn(qkv_w[k * TC3 + n]);
    } else {
        int t2 = t - TC3 * CDIM;
        if (t2 < CDIM * CDIM) {
            int n = t2 % CDIM, k = t2 / CDIM;
            g_wproj_h[n * CDIM + pk16(k)] = __float2half_rn(proj_w[k * CDIM + n]);
        }
    }
}

__global__ void prepack_rm(const float* __restrict__ mask,
                           const float* __restrict__ bias_t, int nmask) {
    int t = blockIdx.x * blockDim.x + threadIdx.x;
    int total = nmask * NHEAD * 64 * 64;
    if (t >= total) return;
    int j = t & 63;
    int i = (t >> 6) & 63;
    int h = (t >> 12) & (NHEAD - 1);
    int v = t >> 14;
    float val = -1.0e30f;
    if (i < NTOK && j < NTOK) {
        int ri = i / 7, ci = i - ri * 7;
        int rj = j / 7, cj = j - rj * 7;
        int idx = (ri - rj + 6) * 13 + (ci - cj + 6);
        val = bias_t[idx * NHEAD + h] + mask[(size_t)v * NTOK * NTOK + i * NTOK + j];
    }
    g_rm[t] = val;
}

// ---------------- main kernel ---------------------------------------------
__global__ __launch_bounds__(512, 1) void win_attn_kernel(
    const float* __restrict__ x,      const float* __restrict__ qkv_b,
    const float* __restrict__ proj_b, float* __restrict__ out, int nmask)
{
    extern __shared__ __half smh[];
    __half* XS = smh + OFF_XS;
    __half* Qb = smh + OFF_Q;
    __half* Kb = smh + OFF_K;
    __half* VT = smh + OFF_VT;
    __half* WB = smh + OFF_WB;

    const int w0   = blockIdx.x * 2;
    const int tid  = threadIdx.x;
    const int warp = tid >> 5;
    const int lane = tid & 31;
    const int g    = lane >> 2;
    const int tig  = lane & 3;
    const int t4   = tig * 4;        // frag half-offset within k16 group

    const int mt = warp & 3;         // G1/G4: 32-row tile
    const int ng = warp >> 2;        // G1/G4: 32-col group
    const int r0 = mt * 32;

    // ---------------- phase 0: stage 2 windows of x; zero pads --------------
    {
        for (int u = tid; u < 2 * NTOK * 8; u += 512) {
            int win = u / (NTOK * 8);
            int q = u - win * (NTOK * 8);
            int r = q >> 3, cb = (q & 7) * 16;
            const float4* xr = (const float4*)(x + (size_t)(w0 + win) * NTOK * CDIM
                                               + r * CDIM + cb);
            float4 f0 = xr[0], f1 = xr[1], f2 = xr[2], f3 = xr[3];
            uint4 lo, hi;
            lo.x = h2u(f0.x, f0.y);  lo.y = h2u(f2.x, f2.y);
            lo.z = h2u(f0.z, f0.w);  lo.w = h2u(f2.z, f2.w);
            hi.x = h2u(f1.x, f1.y);  hi.y = h2u(f3.x, f3.y);
            hi.z = h2u(f1.z, f1.w);  hi.w = h2u(f3.z, f3.w);
            uint4* d = (uint4*)(XS + (win * 64 + r) * S + cb);
            d[0] = lo; d[1] = hi;
        }
        uint4 z = {0, 0, 0, 0};
        for (int u = tid; u < 540; u += 512) {           // XS pad rows 49-63,113-127
            int rr = u / 18, c = (u % 18) * 8;
            int row = (rr < 15) ? (49 + rr) : (98 + rr);
            *(uint4*)(XS + row * S + c) = z;
        }
        for (int u = tid; u < 2304; u += 512)            // zero whole VT
            *(uint4*)(VT + u * 8) = z;
    }

    const uint4* wsrc = (const uint4*)g_wqkv_h;          // 2048 uint4 per slice
    uint4 pf[4];
#pragma unroll
    for (int u = 0; u < 4; u++) pf[u] = wsrc[u * 512 + tid];
    __syncthreads();                                     // (1) phase0 done
#pragma unroll
    for (int u = 0; u < 4; u++) {
        int idx = u * 512 + tid;
        *(uint4*)(WB + (idx >> 4) * S + (idx & 15) * 8) = pf[u];
    }
    __syncthreads();                                     // (2) slice 0 staged

    // ---------------- GEMM1: 3 slices of 128 n (Q, K, V), M=128 -------------
    const float scale = 0.17677669529663687f;  // 32^-0.5
#pragma unroll
    for (int s = 0; s < 3; s++) {
        if (s < 2) {
#pragma unroll
            for (int u = 0; u < 4; u++) pf[u] = wsrc[(s + 1) * 2048 + u * 512 + tid];
        }
        float acc[2][4][4];
#pragma unroll
        for (int m = 0; m < 2; m++)
#pragma unroll
            for (int t = 0; t < 4; t++)
                acc[m][t][0] = acc[m][t][1] = acc[m][t][2] = acc[m][t][3] = 0.f;

#pragma unroll
        for (int kk = 0; kk < 8; kk++) {
            const int kc = kk * 16;
            uint2 aA0 = *(uint2*)(XS + (r0 + g)      * S + kc + t4);
            uint2 aB0 = *(uint2*)(XS + (r0 + g + 8)  * S + kc + t4);
            uint2 aA1 = *(uint2*)(XS + (r0 + g + 16) * S + kc + t4);
            uint2 aB1 = *(uint2*)(XS + (r0 + g + 24) * S + kc + t4);
#pragma unroll
            for (int t = 0; t < 4; t++) {
                uint2 b = *(uint2*)(WB + (ng * 32 + t * 8 + g) * S + kc + t4);
                mma16(acc[0][t], aA0, aB0, b);
                mma16(acc[1][t], aA1, aB1, b);
            }
        }
        // epilogue (slice: 0->Q, 1->K, 2->V^T)
#pragma unroll
        for (int m = 0; m < 2; m++) {
            const int rA = r0 + m * 16 + g, rB = rA + 8;
#pragma unroll
            for (int t = 0; t < 4; t++) {
                const int c0 = ng * 32 + t * 8 + 2 * tig;   // even, 0..126
                const int po = pk16(c0);
                const float bb0 = qkv_b[s * 128 + c0], bb1 = qkv_b[s * 128 + c0 + 1];
                float v00 = acc[m][t][0] + bb0, v01 = acc[m][t][1] + bb1;
                float v10 = acc[m][t][2] + bb0, v11 = acc[m][t][3] + bb1;
                if (s == 0) {
                    *(__half2*)(Qb + rA * S + po) = __floats2half2_rn(v00 * scale, v01 * scale);
                    *(__half2*)(Qb + rB * S + po) = __floats2half2_rn(v10 * scale, v11 * scale);
                } else if (s == 1) {
                    *(__half2*)(Kb + rA * S + po) = __floats2half2_rn(v00, v01);
                    *(__half2*)(Kb + rB * S + po) = __floats2half2_rn(v10, v11);
                } else {
                    const int winA = rA >> 6, rlA = rA & 63;
                    if (rlA < NTOK) {
                        VT[c0 * S + winA * 64 + pk16(rlA)]       = __float2half_rn(v00);
                        VT[(c0 + 1) * S + winA * 64 + pk16(rlA)] = __float2half_rn(v01);
                    }
                    const int winB = rB >> 6, rlB = rB & 63;
                    if (rlB < NTOK) {
                        VT[c0 * S + winB * 64 + pk16(rlB)]       = __float2half_rn(v10);
                        VT[(c0 + 1) * S + winB * 64 + pk16(rlB)] = __float2half_rn(v11);
                    }
                }
            }
        }
        __syncthreads();                                 // slice consumed
        if (s < 2) {
#pragma unroll
            for (int u = 0; u < 4; u++) {
                int idx = u * 512 + tid;
                *(uint4*)(WB + (idx >> 4) * S + (idx & 15) * 8) = pf[u];
            }
            __syncthreads();                             // next slice staged
        }
    }

    // prefetch proj_w to regs (WB idle until G4)
    {
        const uint4* psrc = (const uint4*)g_wproj_h;
#pragma unroll
        for (int u = 0; u < 4; u++) pf[u] = psrc[u * 512 + tid];
    }

    // ---------------- attention: warp = (head, m-tile); win 0 then 1 --------
    {
        const int h   = warp >> 2;
        const int mt2 = warp & 3;
        const int rb2 = mt2 * 16;
#pragma unroll
        for (int win = 0; win < 2; win++) {
            const int wbase = win * 64;
            // GEMM2: logits [16][64] in regs
            float lv[8][4];
#pragma unroll
            for (int t = 0; t < 8; t++) lv[t][0] = lv[t][1] = lv[t][2] = lv[t][3] = 0.f;
#pragma unroll
            for (int kk = 0; kk < 2; kk++) {
                const int kc = h * 32 + kk * 16;
                uint2 aA = *(uint2*)(Qb + (wbase + rb2 + g)     * S + kc + t4);
                uint2 aB = *(uint2*)(Qb + (wbase + rb2 + g + 8) * S + kc + t4);
#pragma unroll
                for (int t = 0; t < 8; t++) {
                    uint2 b = *(uint2*)(Kb + (wbase + t * 8 + g) * S + kc + t4);
                    mma16(lv[t], aA, aB, b);
                }
            }
            // + rpb+mask, softmax in regs
            const int v = (w0 + win) % nmask;
            const float* rm0 = g_rm + ((size_t)((v * NHEAD + h) * 64 + rb2 + g)) * 64;
            const float* rm1 = rm0 + 8 * 64;
            float mx0 = -3.0e38f, mx1 = -3.0e38f;
#pragma unroll
            for (int t = 0; t < 8; t++) {
                const int j0 = t * 8 + 2 * tig;
                float2 q0 = *(const float2*)(rm0 + j0);
                float2 q1 = *(const float2*)(rm1 + j0);
                lv[t][0] += q0.x; lv[t][1] += q0.y;
                lv[t][2] += q1.x; lv[t][3] += q1.y;
                mx0 = fmaxf(mx0, fmaxf(lv[t][0], lv[t][1]));
                mx1 = fmaxf(mx1, fmaxf(lv[t][2], lv[t][3]));
            }
            mx0 = fmaxf(mx0, __shfl_xor_sync(0xffffffffu, mx0, 1));
            mx0 = fmaxf(mx0, __shfl_xor_sync(0xffffffffu, mx0, 2));
            mx1 = fmaxf(mx1, __shfl_xor_sync(0xffffffffu, mx1, 1));
            mx1 = fmaxf(mx1, __shfl_xor_sync(0xffffffffu, mx1, 2));
            float s0 = 0.f, s1 = 0.f;
#pragma unroll
            for (int t = 0; t < 8; t++) {
                lv[t][0] = __expf(lv[t][0] - mx0);
                lv[t][1] = __expf(lv[t][1] - mx0);
                lv[t][2] = __expf(lv[t][2] - mx1);
                lv[t][3] = __expf(lv[t][3] - mx1);
                s0 += lv[t][0] + lv[t][1];
                s1 += lv[t][2] + lv[t][3];
            }
            s0 += __shfl_xor_sync(0xffffffffu, s0, 1);
            s0 += __shfl_xor_sync(0xffffffffu, s0, 2);
            s1 += __shfl_xor_sync(0xffffffffu, s1, 1);
            s1 += __shfl_xor_sync(0xffffffffu, s1, 2);
            const float inv0 = 1.0f / s0, inv1 = 1.0f / s1;

            // GEMM3: P from lv regs (C-frag == fp16 A-frag layout)
            float a3[4][4];
#pragma unroll
            for (int t = 0; t < 4; t++) a3[t][0] = a3[t][1] = a3[t][2] = a3[t][3] = 0.f;
#pragma unroll
            for (int kk = 0; kk < 4; kk++) {
                uint2 alo, ahi;
                alo.x = h2u(lv[2 * kk][0],     lv[2 * kk][1]);
                alo.y = h2u(lv[2 * kk + 1][0], lv[2 * kk + 1][1]);
                ahi.x = h2u(lv[2 * kk][2],     lv[2 * kk][3]);
                ahi.y = h2u(lv[2 * kk + 1][2], lv[2 * kk + 1][3]);
#pragma unroll
                for (int t = 0; t < 4; t++) {
                    uint2 b = *(uint2*)(VT + (h * 32 + t * 8 + g) * S
                                        + wbase + kk * 16 + t4);
                    mma16(a3[t], alo, ahi, b);
                }
            }
            // normalize + store attn-out (fp16 packed A for GEMM4)
#pragma unroll
            for (int t = 0; t < 4; t++) {
                const int c0 = h * 32 + t * 8 + 2 * tig;
                const int po = pk16(c0);
                *(__half2*)(XS + (wbase + rb2 + g)     * S + po) =
                    __floats2half2_rn(a3[t][0] * inv0, a3[t][1] * inv0);
                *(__half2*)(XS + (wbase + rb2 + g + 8) * S + po) =
                    __floats2half2_rn(a3[t][2] * inv1, a3[t][3] * inv1);
            }
        }
    }
    // stage proj_w from regs (WB not touched by attention)
#pragma unroll
    for (int u = 0; u < 4; u++) {
        int idx = u * 512 + tid;
        *(uint4*)(WB + (idx >> 4) * S + (idx & 15) * 8) = pf[u];
    }
    __syncthreads();                                     // attn-out + proj staged

    // ---------------- GEMM4: y[128,128] = ao @ proj_w + b, direct STG ------
    {
        float acc[2][4][4];
#pragma unroll
        for (int m = 0; m < 2; m++)
#pragma unroll
            for (int t = 0; t < 4; t++)
                acc[m][t][0] = acc[m][t][1] = acc[m][t][2] = acc[m][t][3] = 0.f;
#pragma unroll
        for (int kk = 0; kk < 8; kk++) {
            const int kc = kk * 16;
            uint2 aA0 = *(uint2*)(XS + (r0 + g)      * S + kc + t4);
            uint2 aB0 = *(uint2*)(XS + (r0 + g + 8)  * S + kc + t4);
            uint2 aA1 = *(uint2*)(XS + (r0 + g + 16) * S + kc + t4);
            uint2 aB1 = *(uint2*)(XS + (r0 + g + 24) * S + kc + t4);
#pragma unroll
            for (int t = 0; t < 4; t++) {
                uint2 b = *(uint2*)(WB + (ng * 32 + t * 8 + g) * S + kc + t4);
                mma16(acc[0][t], aA0, aB0, b);
                mma16(acc[1][t], aA1, aB1, b);
            }
        }
#pragma unroll
        for (int m = 0; m < 2; m++) {
            const int rA = r0 + m * 16 + g, rB = rA + 8;
            const int winA = rA >> 6, rlA = rA & 63;
            const int winB = rB >> 6, rlB = rB & 63;
#pragma unroll
            for (int t = 0; t < 4; t++) {
                const int c0 = ng * 32 + t * 8 + 2 * tig;
                const float b0 = proj_b[c0], b1 = proj_b[c0 + 1];
                if (rlA < NTOK)
                    *(float2*)(out + (size_t)(w0 + winA) * NTOK * CDIM + rlA * CDIM + c0) =
                        make_float2(acc[m][t][0] + b0, acc[m][t][1] + b1);
                if (rlB < NTOK)
                    *(float2*)(out + (size_t)(w0 + winB) * NTOK * CDIM + rlB * CDIM + c0) =
                        make_float2(acc[m][t][2] + b0, acc[m][t][3] + b1);
            }
        }
    }
}

extern "C" void kernel_launch(void* const* d_in, const int* in_sizes, int n_in,
                              void* d_out, int out_size) {
    const float* x      = (const float*)d_in[0];
    const float* qkv_w  = (const float*)d_in[1];
    const float* qkv_b  = (const float*)d_in[2];
    const float* proj_w = (const float*)d_in[3];
    const float* proj_b = (const float*)d_in[4];
    const float* bias_t = (const float*)d_in[5];
    const float* mask   = (const float*)d_in[6];
    float* out = (float*)d_out;

    const int bw    = in_sizes[0] / (NTOK * CDIM);   // 4096
    const int nmask = in_sizes[6] / (NTOK * NTOK);   // 64

    prepack_w<<<(TC3 * CDIM + CDIM * CDIM + 255) / 256, 256>>>(qkv_w, proj_w);
    {
        int total = nmask * NHEAD * 64 * 64;
        prepack_rm<<<(total + 255) / 256, 256>>>(mask, bias_t, nmask);
    }

    const size_t smem = SMEMH * sizeof(__half);      // 184320 B
    cudaFuncSetAttribute(win_attn_kernel,
                         cudaFuncAttributeMaxDynamicSharedMemorySize, (int)smem);
    win_attn_kernel<<<bw / 2, 512, smem>>>(x, qkv_b, proj_b, out, nmask);
}

// round 11
// speedup vs baseline: 2.6648x; 1.0915x over previous
#include <cuda_runtime.h>
#include <cuda_fp16.h>
#include <cstdint>

// ---------------------------------------------------------------------------
// Swin WindowAttention, fused FP16 mma.sync kernel (m16n8k16), round 11.
// 2 CTAs/SM (256 thr, 128 regs, 112.6 KB smem each): cross-CTA overlap of
// barriers/staging/softmax tails. 1 window per CTA, 32x32 G1/G4 warp tiles.
// ---------------------------------------------------------------------------

namespace {
constexpr int NTOK  = 49;
constexpr int CDIM  = 128;
constexpr int NHEAD = 4;
constexpr int TC3   = 384;
constexpr int MAXW  = 64;
constexpr int S     = 144;   // fp16-unit stride, conflict-free (8g+2tig distinct)
constexpr int SVT   = 80;    // VT stride

constexpr int OFF_XS = 0;                    // [64][144] x, then attn-out
constexpr int OFF_Q  = OFF_XS + 64 * S;      // 9216
constexpr int OFF_K  = OFF_Q  + 64 * S;      // 18432
constexpr int OFF_VT = OFF_K  + 64 * S;      // 27648  [128][80]
constexpr int OFF_WB = OFF_VT + 128 * SVT;   // 37888  [128][144] W slice
constexpr int SMEMH  = OFF_WB + 128 * S;     // 56320 halfs = 112640 B
}

__device__ __half g_wqkv_h[TC3 * CDIM];            // [n=384][pk16(k=128)]
__device__ __half g_wproj_h[CDIM * CDIM];          // [n=128][pk16(k=128)]
__device__ float  g_rm[MAXW * NHEAD * 64 * 64];    // rpb+mask, padded -1e30

// k-interleave within 16-group: 4 halfs at offset 4t = k{2t,2t+1,2t+8,2t+9}
__device__ __forceinline__ int pk16(int k) {
    return (k & ~15) | (((k >> 1) & 3) << 2) | ((k & 8) >> 2) | (k & 1);
}

__device__ __forceinline__ uint32_t h2u(float a, float b) {
    __half2 h = __floats2half2_rn(a, b);
    return *reinterpret_cast<uint32_t*>(&h);
}

__device__ __forceinline__ void mma16(float* c, uint2 alo, uint2 ahi, uint2 b) {
    asm volatile(
        "mma.sync.aligned.m16n8k16.row.col.f32.f16.f16.f32 "
        "{%0,%1,%2,%3}, {%4,%5,%6,%7}, {%8,%9}, {%0,%1,%2,%3};"
        : "+f"(c[0]), "+f"(c[1]), "+f"(c[2]), "+f"(c[3])
        : "r"(alo.x), "r"(ahi.x), "r"(alo.y), "r"(ahi.y), "r"(b.x), "r"(b.y));
}

// ---------------- prepack kernels ------------------------------------------
__global__ void prepack_w(const float* __restrict__ qkv_w,
                          const float* __restrict__ proj_w) {
    int t = blockIdx.x * blockDim.x + threadIdx.x;
    if (t < TC3 * CDIM) {
        int n = t % TC3, k = t / TC3;
        g_wqkv_h[n * CDIM + pk16(k)] = __float2half_rn(qkv_w[k * TC3 + n]);
    } else {
        int t2 = t - TC3 * CDIM;
        if (t2 < CDIM * CDIM) {
            int n = t2 % CDIM, k = t2 / CDIM;
            g_wproj_h[n * CDIM + pk16(k)] = __float2half_rn(proj_w[k * CDIM + n]);
        }
    }
}

__global__ void prepack_rm(const float* __restrict__ mask,
                           const float* __restrict__ bias_t, int nmask) {
    int t = blockIdx.x * blockDim.x + threadIdx.x;
    int total = nmask * NHEAD * 64 * 64;
    if (t >= total) return;
    int j = t & 63;
    int i = (t >> 6) & 63;
    int h = (t >> 12) & (NHEAD - 1);
    int v = t >> 14;
    float val = -1.0e30f;
    if (i < NTOK && j < NTOK) {
        int ri = i / 7, ci = i - ri * 7;
        int rj = j / 7, cj = j - rj * 7;
        int idx = (ri - rj + 6) * 13 + (ci - cj + 6);
        val = bias_t[idx * NHEAD + h] + mask[(size_t)v * NTOK * NTOK + i * NTOK + j];
    }
    g_rm[t] = val;
}

// ---------------- main kernel ---------------------------------------------
__global__ __launch_bounds__(256, 2) void win_attn_kernel(
    const float* __restrict__ x,      const float* __restrict__ qkv_b,
    const float* __restrict__ proj_b, float* __restrict__ out, int nmask)
{
    extern __shared__ __half smh[];
    __half* XS = smh + OFF_XS;
    __half* Qb = smh + OFF_Q;
    __half* Kb = smh + OFF_K;
    __half* VT = smh + OFF_VT;
    __half* WB = smh + OFF_WB;

    const int w    = blockIdx.x;
    const int tid  = threadIdx.x;
    const int warp = tid >> 5;
    const int lane = tid & 31;
    const int g    = lane >> 2;
    const int tig  = lane & 3;
    const int t4   = tig * 4;        // frag half-offset within k16 group

    const int mt = warp & 1;         // G1/G4: 32-row tile (0..1)
    const int ng = warp >> 1;        // G1/G4: 32-col group (0..3)
    const int r0 = mt * 32;

    // ---------------- phase 0: stage x; zero pads ---------------------------
    {
        const float* xg = x + (size_t)w * NTOK * CDIM;
        for (int u = tid; u < NTOK * 8; u += 256) {
            int r = u >> 3, cb = (u & 7) * 16;
            const float4* xr = (const float4*)(xg + r * CDIM + cb);
            float4 f0 = xr[0], f1 = xr[1], f2 = xr[2], f3 = xr[3];
            uint4 lo, hi;
            lo.x = h2u(f0.x, f0.y);  lo.y = h2u(f2.x, f2.y);
            lo.z = h2u(f0.z, f0.w);  lo.w = h2u(f2.z, f2.w);
            hi.x = h2u(f1.x, f1.y);  hi.y = h2u(f3.x, f3.y);
            hi.z = h2u(f1.z, f1.w);  hi.w = h2u(f3.z, f3.w);
            uint4* d = (uint4*)(XS + r * S + cb);
            d[0] = lo; d[1] = hi;
        }
        uint4 z = {0, 0, 0, 0};
        for (int u = tid; u < 270; u += 256)             // XS pad rows 49..63
            *(uint4*)(XS + NTOK * S + u * 8) = z;
        for (int u = tid; u < 1280; u += 256)            // zero whole VT
            *(uint4*)(VT + u * 8) = z;
    }

    const uint4* wsrc = (const uint4*)g_wqkv_h;          // 2048 uint4 per slice
    uint4 pf[8];
#pragma unroll
    for (int u = 0; u < 8; u++) pf[u] = wsrc[u * 256 + tid];
    __syncthreads();                                     // (1) phase0 done
#pragma unroll
    for (int u = 0; u < 8; u++) {
        int idx = u * 256 + tid;
        *(uint4*)(WB + (idx >> 4) * S + (idx & 15) * 8) = pf[u];
    }
    __syncthreads();                                     // (2) slice 0 staged

    // ---------------- GEMM1: 3 slices of 128 n (Q, K, V) -------------------
    const float scale = 0.17677669529663687f;  // 32^-0.5
#pragma unroll
    for (int s = 0; s < 3; s++) {
        if (s < 2) {
#pragma unroll
            for (int u = 0; u < 8; u++) pf[u] = wsrc[(s + 1) * 2048 + u * 256 + tid];
        }
        float acc[2][4][4];
#pragma unroll
        for (int m = 0; m < 2; m++)
#pragma unroll
            for (int t = 0; t < 4; t++)
                acc[m][t][0] = acc[m][t][1] = acc[m][t][2] = acc[m][t][3] = 0.f;

#pragma unroll
        for (int kk = 0; kk < 8; kk++) {
            const int kc = kk * 16;
            uint2 aA0 = *(uint2*)(XS + (r0 + g)      * S + kc + t4);
            uint2 aB0 = *(uint2*)(XS + (r0 + g + 8)  * S + kc + t4);
            uint2 aA1 = *(uint2*)(XS + (r0 + g + 16) * S + kc + t4);
            uint2 aB1 = *(uint2*)(XS + (r0 + g + 24) * S + kc + t4);
#pragma unroll
            for (int t = 0; t < 4; t++) {
                uint2 b = *(uint2*)(WB + (ng * 32 + t * 8 + g) * S + kc + t4);
                mma16(acc[0][t], aA0, aB0, b);
                mma16(acc[1][t], aA1, aB1, b);
            }
        }
        // epilogue (slice: 0->Q, 1->K, 2->V^T)
#pragma unroll
        for (int m = 0; m < 2; m++) {
            const int rA = r0 + m * 16 + g, rB = rA + 8;
#pragma unroll
            for (int t = 0; t < 4; t++) {
                const int c0 = ng * 32 + t * 8 + 2 * tig;   // even, 0..126
                const int po = pk16(c0);
                const float bb0 = qkv_b[s * 128 + c0], bb1 = qkv_b[s * 128 + c0 + 1];
                float v00 = acc[m][t][0] + bb0, v01 = acc[m][t][1] + bb1;
                float v10 = acc[m][t][2] + bb0, v11 = acc[m][t][3] + bb1;
                if (s == 0) {
                    *(__half2*)(Qb + rA * S + po) = __floats2half2_rn(v00 * scale, v01 * scale);
                    *(__half2*)(Qb + rB * S + po) = __floats2half2_rn(v10 * scale, v11 * scale);
                } else if (s == 1) {
                    *(__half2*)(Kb + rA * S + po) = __floats2half2_rn(v00, v01);
                    *(__half2*)(Kb + rB * S + po) = __floats2half2_rn(v10, v11);
                } else {
                    if (rA < NTOK) {
                        VT[c0 * SVT + pk16(rA)]       = __float2half_rn(v00);
                        VT[(c0 + 1) * SVT + pk16(rA)] = __float2half_rn(v01);
                    }
                    if (rB < NTOK) {
                        VT[c0 * SVT + pk16(rB)]       = __float2half_rn(v10);
                        VT[(c0 + 1) * SVT + pk16(rB)] = __float2half_rn(v11);
                    }
                }
            }
        }
        __syncthreads();                                 // slice consumed
        if (s < 2) {
#pragma unroll
            for (int u = 0; u < 8; u++) {
                int idx = u * 256 + tid;
                *(uint4*)(WB + (idx >> 4) * S + (idx & 15) * 8) = pf[u];
            }
            __syncthreads();                             // next slice staged
        }
    }

    // prefetch proj_w to regs (WB idle until G4)
    {
        const uint4* psrc = (const uint4*)g_wproj_h;
#pragma unroll
        for (int u = 0; u < 8; u++) pf[u] = psrc[u * 256 + tid];
    }

    // ---------------- attention: 8 warps x 2 tasks of (head, m-tile) --------
#pragma unroll
    for (int task = 0; task < 2; task++) {
        const int tk  = warp + task * 8;     // 0..15
        const int h   = tk >> 2;
        const int mt2 = tk & 3;
        const int rb2 = mt2 * 16;

        // GEMM2: logits [16][64] in regs
        float lv[8][4];
#pragma unroll
        for (int t = 0; t < 8; t++) lv[t][0] = lv[t][1] = lv[t][2] = lv[t][3] = 0.f;
#pragma unroll
        for (int kk = 0; kk < 2; kk++) {
            const int kc = h * 32 + kk * 16;
            uint2 aA = *(uint2*)(Qb + (rb2 + g)     * S + kc + t4);
            uint2 aB = *(uint2*)(Qb + (rb2 + g + 8) * S + kc + t4);
#pragma unroll
            for (int t = 0; t < 8; t++) {
                uint2 b = *(uint2*)(Kb + (t * 8 + g) * S + kc + t4);
                mma16(lv[t], aA, aB, b);
            }
        }
        // + rpb+mask, softmax in regs
        const int v = w % nmask;
        const float* rm0 = g_rm + ((size_t)((v * NHEAD + h) * 64 + rb2 + g)) * 64;
        const float* rm1 = rm0 + 8 * 64;
        float mx0 = -3.0e38f, mx1 = -3.0e38f;
#pragma unroll
        for (int t = 0; t < 8; t++) {
            const int j0 = t * 8 + 2 * tig;
            float2 q0 = *(const float2*)(rm0 + j0);
            float2 q1 = *(const float2*)(rm1 + j0);
            lv[t][0] += q0.x; lv[t][1] += q0.y;
            lv[t][2] += q1.x; lv[t][3] += q1.y;
            mx0 = fmaxf(mx0, fmaxf(lv[t][0], lv[t][1]));
            mx1 = fmaxf(mx1, fmaxf(lv[t][2], lv[t][3]));
        }
        mx0 = fmaxf(mx0, __shfl_xor_sync(0xffffffffu, mx0, 1));
        mx0 = fmaxf(mx0, __shfl_xor_sync(0xffffffffu, mx0, 2));
        mx1 = fmaxf(mx1, __shfl_xor_sync(0xffffffffu, mx1, 1));
        mx1 = fmaxf(mx1, __shfl_xor_sync(0xffffffffu, mx1, 2));
        float s0 = 0.f, s1 = 0.f;
#pragma unroll
        for (int t = 0; t < 8; t++) {
            lv[t][0] = __expf(lv[t][0] - mx0);
            lv[t][1] = __expf(lv[t][1] - mx0);
            lv[t][2] = __expf(lv[t][2] - mx1);
            lv[t][3] = __expf(lv[t][3] - mx1);
            s0 += lv[t][0] + lv[t][1];
            s1 += lv[t][2] + lv[t][3];
        }
        s0 += __shfl_xor_sync(0xffffffffu, s0, 1);
        s0 += __shfl_xor_sync(0xffffffffu, s0, 2);
        s1 += __shfl_xor_sync(0xffffffffu, s1, 1);
        s1 += __shfl_xor_sync(0xffffffffu, s1, 2);
        const float inv0 = 1.0f / s0, inv1 = 1.0f / s1;

        // GEMM3: P from lv regs (C-frag == fp16 A-frag layout)
        float a3[4][4];
#pragma unroll
        for (int t = 0; t < 4; t++) a3[t][0] = a3[t][1] = a3[t][2] = a3[t][3] = 0.f;
#pragma unroll
        for (int kk = 0; kk < 4; kk++) {
            uint2 alo, ahi;
            alo.x = h2u(lv[2 * kk][0],     lv[2 * kk][1]);
            alo.y = h2u(lv[2 * kk + 1][0], lv[2 * kk + 1][1]);
            ahi.x = h2u(lv[2 * kk][2],     lv[2 * kk][3]);
            ahi.y = h2u(lv[2 * kk + 1][2], lv[2 * kk + 1][3]);
#pragma unroll
            for (int t = 0; t < 4; t++) {
                uint2 b = *(uint2*)(VT + (h * 32 + t * 8 + g) * SVT + kk * 16 + t4);
                mma16(a3[t], alo, ahi, b);
            }
        }
        // normalize + store attn-out (fp16 packed A for GEMM4)
#pragma unroll
        for (int t = 0; t < 4; t++) {
            const int c0 = h * 32 + t * 8 + 2 * tig;
            const int po = pk16(c0);
            *(__half2*)(XS + (rb2 + g)     * S + po) =
                __floats2half2_rn(a3[t][0] * inv0, a3[t][1] * inv0);
            *(__half2*)(XS + (rb2 + g + 8) * S + po) =
                __floats2half2_rn(a3[t][2] * inv1, a3[t][3] * inv1);
        }
    }
    __syncthreads();                                     // attention done
    // stage proj_w from regs
#pragma unroll
    for (int u = 0; u < 8; u++) {
        int idx = u * 256 + tid;
        *(uint4*)(WB + (idx >> 4) * S + (idx & 15) * 8) = pf[u];
    }
    __syncthreads();                                     // proj staged

    // ---------------- GEMM4: y[64,128] = ao @ proj_w + b, direct STG -------
    {
        float acc[2][4][4];
#pragma unroll
        for (int m = 0; m < 2; m++)
#pragma unroll
            for (int t = 0; t < 4; t++)
                acc[m][t][0] = acc[m][t][1] = acc[m][t][2] = acc[m][t][3] = 0.f;
#pragma unroll
        for (int kk = 0; kk < 8; kk++) {
            const int kc = kk * 16;
            uint2 aA0 = *(uint2*)(XS + (r0 + g)      * S + kc + t4);
            uint2 aB0 = *(uint2*)(XS + (r0 + g + 8)  * S + kc + t4);
            uint2 aA1 = *(uint2*)(XS + (r0 + g + 16) * S + kc + t4);
            uint2 aB1 = *(uint2*)(XS + (r0 + g + 24) * S + kc + t4);
#pragma unroll
            for (int t = 0; t < 4; t++) {
                uint2 b = *(uint2*)(WB + (ng * 32 + t * 8 + g) * S + kc + t4);
                mma16(acc[0][t], aA0, aB0, b);
                mma16(acc[1][t], aA1, aB1, b);
            }
        }
        float* og = out + (size_t)w * NTOK * CDIM;
#pragma unroll
        for (int m = 0; m < 2; m++) {
            const int rA = r0 + m * 16 + g, rB = rA + 8;
#pragma unroll
            for (int t = 0; t < 4; t++) {
                const int c0 = ng * 32 + t * 8 + 2 * tig;
                const float b0 = proj_b[c0], b1 = proj_b[c0 + 1];
                if (rA < NTOK)
                    *(float2*)(og + rA * CDIM + c0) =
                        make_float2(acc[m][t][0] + b0, acc[m][t][1] + b1);
                if (rB < NTOK)
                    *(float2*)(og + rB * CDIM + c0) =
                        make_float2(acc[m][t][2] + b0, acc[m][t][3] + b1);
            }
        }
    }
}

extern "C" void kernel_launch(void* const* d_in, const int* in_sizes, int n_in,
                              void* d_out, int out_size) {
    const float* x      = (const float*)d_in[0];
    const float* qkv_w  = (const float*)d_in[1];
    const float* qkv_b  = (const float*)d_in[2];
    const float* proj_w = (const float*)d_in[3];
    const float* proj_b = (const float*)d_in[4];
    const float* bias_t = (const float*)d_in[5];
    const float* mask   = (const float*)d_in[6];
    float* out = (float*)d_out;

    const int bw    = in_sizes[0] / (NTOK * CDIM);   // 4096
    const int nmask = in_sizes[6] / (NTOK * NTOK);   // 64

    prepack_w<<<(TC3 * CDIM + CDIM * CDIM + 255) / 256, 256>>>(qkv_w, proj_w);
    {
        int total = nmask * NHEAD * 64 * 64;
        prepack_rm<<<(total + 255) / 256, 256>>>(mask, bias_t, nmask);
    }

    const size_t smem = SMEMH * sizeof(__half);      // 112640 B per CTA
    cudaFuncSetAttribute(win_attn_kernel,
                         cudaFuncAttributeMaxDynamicSharedMemorySize, (int)smem);
    win_attn_kernel<<<bw, 256, smem>>>(x, qkv_b, proj_b, out, nmask);
}